// round 7
// baseline (speedup 1.0000x reference)
#include <cuda_runtime.h>

#define NB    32
#define NN    8192
#define NCLIP 256
#define CAPB  512         // per-batch capacity (mean 256, 16-sigma margin)
#define NW    16          // mask words per column (CAPB/32)
#define FULL  0xffffffffu

// Scratch (__device__ globals; allocation-free rule)
__device__ int   g_off[NB + 1];
__device__ float g_gsc[NN];   // per-batch desc-sorted scores, compact by g_off
__device__ float g_gs[NN];    // sorted box starts
__device__ float g_ge[NN];    // sorted box ends

// ---------------------------------------------------------------------------
// K1: blocks 0..31 -> gt_dist ; blocks 32..63 -> per-batch stable sort
// ---------------------------------------------------------------------------
__global__ void k1_kernel(const float* __restrict__ gt,
                          const int*   __restrict__ bidx,
                          const float* __restrict__ pred,
                          const float* __restrict__ score,
                          float* __restrict__ out) {
    int blk = blockIdx.x;
    int tid = threadIdx.x;
    if (blk < NB) {
        int b = blk, c = tid;
        float s = gt[2 * b];
        float e = gt[2 * b + 1];
        float len  = 256.0f * (e - s);
        float cen0 = 256.0f * s;
        float cen1 = 256.0f * e;
        float cen2 = 128.0f * (s + e);
        float sgS  = 0.25f * len;
        float sgM  = 0.21f * len;
        float inv2sS = 1.0f / (2.0f * sgS * sgS);
        float inv2sM = 1.0f / (2.0f * sgM * sgM);
        float fc = (float)c;
        float d0 = fc - cen0, d1 = fc - cen1, d2 = fc - cen2;
        float* o = out + ((size_t)b * NCLIP + c) * 3;
        o[0] = expf(-d0 * d0 * inv2sS);
        o[1] = expf(-d1 * d1 * inv2sS);
        o[2] = expf(-d2 * d2 * inv2sM);
        return;
    }
    // per-batch sort CTA
    int b = blk - NB;
    __shared__ int sob, soe;
    __shared__ float rsc[CAPB];
    if (tid == 0) {
        int lo = 0, hi = NN;                    // lower_bound(bidx, b)
        while (lo < hi) { int m = (lo + hi) >> 1; if (bidx[m] < b) lo = m + 1; else hi = m; }
        int ob = lo;
        hi = NN;                                 // lower_bound(bidx, b+1)
        while (lo < hi) { int m = (lo + hi) >> 1; if (bidx[m] < b + 1) lo = m + 1; else hi = m; }
        sob = ob; soe = lo;
        g_off[b] = ob;
        if (b == NB - 1) g_off[NB] = NN;
    }
    __syncthreads();
    int ob = sob;
    int cnt = soe - ob;
    if (cnt > CAPB) cnt = CAPB;
    for (int t = tid; t < cnt; t += 256) rsc[t] = score[ob + t];
    __syncthreads();
    for (int t = tid; t < cnt; t += 256) {
        float si = rsc[t];
        int wr = 0;
        for (int j = 0; j < cnt; j++) {
            float sj = rsc[j];
            wr += (sj > si) || (sj == si && j < t);
        }
        float2 p2 = ((const float2*)pred)[ob + t];
        g_gsc[ob + wr] = si;
        g_gs[ob + wr]  = p2.x;
        g_ge[ob + wr]  = p2.y;
    }
}

// ---------------------------------------------------------------------------
// K2: one CTA per batch. Phase 1: global rank via 31 binary searches per
// element over all batches' sorted scores (smem). Phase 2: triangular IoU
// suppression masks (smem overlay). Phase 3: ballot-fixpoint greedy scan.
// Phase 4: writeback.
// ---------------------------------------------------------------------------
__global__ void k2_kernel(float* __restrict__ out) {
    __shared__ __align__(16) unsigned buf[NN];   // 32KB: scores, then masks
    __shared__ int   soff[NB + 1];
    __shared__ float ss[CAPB], se[CAPB], sl[CAPB], ssc[CAPB];
    __shared__ int   sgr[CAPB];
    __shared__ unsigned skeep[NW];

    int b   = blockIdx.x;
    int tid = threadIdx.x;
    float* allsc = (float*)buf;
    unsigned* sup = buf;

    if (tid <= NB) soff[tid] = g_off[tid];
    {   // load all sorted scores (coalesced float4)
        float4* d4 = (float4*)allsc;
        const float4* s4 = (const float4*)g_gsc;
        for (int k = tid; k < NN / 4; k += 256) d4[k] = s4[k];
    }
    __syncthreads();

    int ob  = soff[b];
    int cnt = soff[b + 1] - ob;
    if (cnt > CAPB) cnt = CAPB;
    if (cnt == 0) return;
    int nG = (cnt + 31) >> 5;

    // Phase 1: per-element global rank + stage sorted boxes/scores
    for (int t = tid; t < cnt; t += 256) {
        float si = allsc[ob + t];
        float s  = g_gs[ob + t];
        float e  = g_ge[ob + t];
        ss[t] = s; se[t] = e; sl[t] = e - s; ssc[t] = si;
        int r = t;                              // within-batch stable rank
        for (int b2 = 0; b2 < NB; b2++) {
            if (b2 == b) continue;
            int o2 = soff[b2];
            int n2 = soff[b2 + 1] - o2;
            int lo = 0, hi = n2;
            if (b2 < b) {                       // countGE (desc array)
                while (lo < hi) { int m = (lo + hi) >> 1; if (allsc[o2 + m] >= si) lo = m + 1; else hi = m; }
            } else {                            // countGT
                while (lo < hi) { int m = (lo + hi) >> 1; if (allsc[o2 + m] >  si) lo = m + 1; else hi = m; }
            }
            r += lo;
        }
        sgr[t] = r;
    }
    __syncthreads();   // all allsc reads done -> safe to overlay with masks

    // Phase 2: build lower-triangle suppression masks (word-major)
    for (int g = 0; g < nG; g++) {
        int W = 32 * (g + 1);
        for (int p = tid; p < W; p += 256) {
            int w  = p >> 5;
            int jl = p & 31;
            int j  = 32 * g + jl;
            if (j >= cnt) continue;
            float sj = ss[j], ej = se[j], lj = sl[j];
            unsigned word = 0;
            int rb = 32 * w;
#pragma unroll
            for (int k = 0; k < 32; k++) {
                float si_ = ss[rb + k], ei_ = se[rb + k], li_ = sl[rb + k];
                float interc = fmaxf(fminf(ej, ei_) - fmaxf(sj, si_), 0.0f);
                float uni = lj + li_ - interc;
                float um  = fmaxf(uni, 1e-8f);
                float diff = interc - 0.5f * um;
                bool sp;
                if (fabsf(diff) <= 1e-6f * um) sp = (interc / um) > 0.5f;
                else                           sp = diff > 0.0f;
                if (sp) word |= 1u << k;
            }
            if (w == g) word &= (1u << jl) - 1u;   // only rows i < j
            sup[w * CAPB + j] = word;
        }
    }
    __syncthreads();

    // Phase 3: ballot-fixpoint greedy scan (warp 0)
    if (tid < 32) {
        int lane = tid;
        for (int g = 0; g < nG; g++) {
            int j = 32 * g + lane;
            bool valid = j < cnt;
            unsigned dead = 0;
            for (int w = 0; w < g; w++)
                dead |= valid ? (sup[w * CAPB + j] & skeep[w]) : 0u;
            unsigned pend = valid ? sup[g * CAPB + j] : 0u;
            bool alive0 = valid && (dead == 0u);
            unsigned M = __ballot_sync(FULL, alive0);
            for (;;) {
                unsigned Mn = __ballot_sync(FULL, alive0 && ((pend & M) == 0u));
                if (Mn == M) break;
                M = Mn;
            }
            skeep[g] = M;
            __syncwarp();
        }
    }
    __syncthreads();

    // Phase 4: writeback at global sorted positions
    float* obds = out + (size_t)NB * NCLIP * 3;
    float* osc  = obds + 2 * NN;
    for (int t = tid; t < cnt; t += 256) {
        int gr = sgr[t];
        float f = ((skeep[t >> 5] >> (t & 31)) & 1u) ? 1.0f : 0.0f;
        obds[2 * gr]     = ss[t] * f;
        obds[2 * gr + 1] = se[t] * f;
        osc[gr]          = ssc[t] * f;
    }
}

// ---------------------------------------------------------------------------
extern "C" void kernel_launch(void* const* d_in, const int* in_sizes, int n_in,
                              void* d_out, int out_size) {
    const float* gt    = (const float*)d_in[0];
    const float* pred  = (const float*)d_in[1];
    const float* score = (const float*)d_in[2];
    const int*   bidx  = (const int*)d_in[3];
    float* out = (float*)d_out;

    k1_kernel<<<2 * NB, 256>>>(gt, bidx, pred, score, out);
    k2_kernel<<<NB, 256>>>(out);
}

// round 9
// speedup vs baseline: 1.2074x; 1.2074x over previous
#include <cuda_runtime.h>

#define NB    32
#define NN    8192
#define NCLIP 256
#define JCH   32          // j-chunks (aligned with 256-thread i-blocks)
#define JSZ   256
#define CAPB  512         // per-batch capacity (mean 256, 16-sigma margin)
#define MAXG  12          // max 32-column groups per batch (cnt <= 384 w/ margin)
#define FULL  0xffffffffu

// Scratch (__device__ globals; allocation-free rule)
__device__ int      g_off[NB + 1];
__device__ int      g_part[JCH * NN];          // partial global ranks
__device__ float    g_ss[NN + CAPB];           // per-batch sorted starts (+pad)
__device__ float    g_se[NN + CAPB];           // per-batch sorted ends   (+pad)
__device__ float    g_ssc[NN];                 // sorted scores
__device__ int      g_sgr[NN];                 // global rank per sorted slot
__device__ unsigned g_sup[NB * MAXG * CAPB];   // masks, w-major: ((b*MAXG+w)*CAPB+j)

// ---------------------------------------------------------------------------
// K1: blocks 0..31 gt_dist | rest: partial rank, chunk-aligned compares
// ---------------------------------------------------------------------------
__global__ void k1_kernel(const float* __restrict__ gt,
                          const float* __restrict__ score,
                          float* __restrict__ out) {
    int blk = blockIdx.x;
    int tid = threadIdx.x;
    if (blk < NB) {
        int b = blk, c = tid;
        float s = gt[2 * b];
        float e = gt[2 * b + 1];
        float len  = 256.0f * (e - s);
        float cen0 = 256.0f * s;
        float cen1 = 256.0f * e;
        float cen2 = 128.0f * (s + e);
        float sgS  = 0.25f * len;
        float sgM  = 0.21f * len;
        float inv2sS = 1.0f / (2.0f * sgS * sgS);
        float inv2sM = 1.0f / (2.0f * sgM * sgM);
        float fc = (float)c;
        float d0 = fc - cen0, d1 = fc - cen1, d2 = fc - cen2;
        float* o = out + ((size_t)b * NCLIP + c) * 3;
        o[0] = expf(-d0 * d0 * inv2sS);
        o[1] = expf(-d1 * d1 * inv2sS);
        o[2] = expf(-d2 * d2 * inv2sM);
        return;
    }
    int q    = blk - NB;              // 0..1023
    int jc   = q & (JCH - 1);
    int iblk = q >> 5;
    int i    = iblk * 256 + tid;
    float si = score[i];
    const float4* s4 = (const float4*)score + jc * (JSZ / 4);
    int r = 0;
    if (jc < iblk) {                  // all j < i: ties count
#pragma unroll 8
        for (int t = 0; t < JSZ / 4; t++) {
            float4 v = s4[t];
            r += (v.x >= si) + (v.y >= si) + (v.z >= si) + (v.w >= si);
        }
    } else if (jc > iblk) {           // all j > i: strict
#pragma unroll 8
        for (int t = 0; t < JSZ / 4; t++) {
            float4 v = s4[t];
            r += (v.x > si) + (v.y > si) + (v.z > si) + (v.w > si);
        }
    } else {                          // diagonal: exact tie-break
        int jbase = jc * JSZ;
#pragma unroll 8
        for (int t = 0; t < JSZ / 4; t++) {
            float4 v = s4[t];
            int j = jbase + 4 * t;
            r += (v.x > si) || (v.x == si && (j + 0) < i);
            r += (v.y > si) || (v.y == si && (j + 1) < i);
            r += (v.z > si) || (v.z == si && (j + 2) < i);
            r += (v.w > si) || (v.w == si && (j + 3) < i);
        }
    }
    g_part[jc * NN + i] = r;
}

// ---------------------------------------------------------------------------
// K2: one CTA per batch — offsets + stable per-batch sort + global rank.
// ---------------------------------------------------------------------------
__global__ void k2_kernel(const int*   __restrict__ bidx,
                          const float* __restrict__ pred,
                          const float* __restrict__ score) {
    __shared__ int sob, soe;
    __shared__ float rsc[CAPB];
    int b   = blockIdx.x;
    int tid = threadIdx.x;
    if (tid == 0) {
        int lo = 0, hi = NN;
        while (lo < hi) { int m = (lo + hi) >> 1; if (bidx[m] < b) lo = m + 1; else hi = m; }
        int ob = lo;
        hi = NN;
        while (lo < hi) { int m = (lo + hi) >> 1; if (bidx[m] < b + 1) lo = m + 1; else hi = m; }
        sob = ob; soe = lo;
        g_off[b] = ob;
        if (b == NB - 1) g_off[NB] = NN;
    }
    __syncthreads();
    int ob  = sob;
    int cnt = soe - ob;
    if (cnt > CAPB) cnt = CAPB;
    for (int t = tid; t < cnt; t += 256) rsc[t] = score[ob + t];
    __syncthreads();
    for (int t = tid; t < cnt; t += 256) {
        float si = rsc[t];
        int wr = 0;
        for (int j = 0; j < cnt; j++) {
            float sj = rsc[j];
            wr += (sj > si) || (sj == si && j < t);
        }
        int i = ob + t;
        int r = 0;
#pragma unroll
        for (int jc = 0; jc < JCH; jc++) r += g_part[jc * NN + i];
        float2 p2 = ((const float2*)pred)[i];
        g_ss[ob + wr]  = p2.x;
        g_se[ob + wr]  = p2.y;
        g_ssc[ob + wr] = si;
        g_sgr[ob + wr] = r;
    }
}

// ---------------------------------------------------------------------------
// K3: mask build. One CTA per (column-group g, batch b). Coalesced w-major
// writes. 256 threads = 32 columns x 8 word-phases.
// ---------------------------------------------------------------------------
__global__ void k3_kernel() {
    int g = blockIdx.x;               // 0..MAXG-1
    int b = blockIdx.y;
    int ob  = g_off[b];
    int cnt = g_off[b + 1] - ob;
    if (cnt > CAPB) cnt = CAPB;
    if (32 * g >= cnt) return;

    __shared__ float ss[32 * MAXG], se_[32 * MAXG], sl[32 * MAXG];
    int tid  = threadIdx.x;
    int rows = 32 * (g + 1);          // rows >= cnt on diagonal are masked out
    for (int i = tid; i < rows; i += 256) {
        float s = g_ss[ob + i], e = g_se[ob + i];   // pad makes OOB-safe
        ss[i] = s; se_[i] = e; sl[i] = e - s;
    }
    __syncthreads();

    int jl = tid & 31;
    int wh = tid >> 5;
    int j  = 32 * g + jl;
    if (j >= cnt) return;
    float sj = ss[j], ej = se_[j], lj = sl[j];
    for (int w = wh; w <= g; w += 8) {
        unsigned word = 0;
        int rb = 32 * w;
#pragma unroll
        for (int k = 0; k < 32; k++) {
            float si_ = ss[rb + k], ei_ = se_[rb + k], li_ = sl[rb + k];
            float interc = fmaxf(fminf(ej, ei_) - fmaxf(sj, si_), 0.0f);
            float uni = lj + li_ - interc;
            float um  = fmaxf(uni, 1e-8f);
            float diff = interc - 0.5f * um;
            bool sp;
            if (fabsf(diff) <= 1e-6f * um) sp = (interc / um) > 0.5f;
            else                           sp = diff > 0.0f;
            if (sp) word |= 1u << k;
        }
        if (w == g) word &= (1u << jl) - 1u;         // only rows i < j
        g_sup[(b * MAXG + w) * CAPB + j] = word;     // coalesced across jl
    }
}

// ---------------------------------------------------------------------------
// K4: ballot-fixpoint greedy scan (warp per batch) + writeback.
// ---------------------------------------------------------------------------
__global__ void k4_kernel(float* __restrict__ out) {
    __shared__ unsigned skeep[MAXG];
    int b    = blockIdx.x;
    int lane = threadIdx.x;
    int ob   = g_off[b];
    int cnt  = g_off[b + 1] - ob;
    if (cnt > CAPB) cnt = CAPB;
    int nG = (cnt + 31) >> 5;

    for (int g = 0; g < nG; g++) {
        int j = 32 * g + lane;
        bool valid = j < cnt;
        unsigned dead = 0;
#pragma unroll
        for (int w = 0; w < MAXG; w++) {             // independent loads -> MLP
            if (w >= g) break;
            dead |= valid ? (g_sup[(b * MAXG + w) * CAPB + j] & skeep[w]) : 0u;
        }
        unsigned pend = valid ? g_sup[(b * MAXG + g) * CAPB + j] : 0u;
        bool alive0 = valid && (dead == 0u);
        unsigned M = __ballot_sync(FULL, alive0);
        for (;;) {                                   // unique fixpoint = greedy
            unsigned Mn = __ballot_sync(FULL, alive0 && ((pend & M) == 0u));
            if (Mn == M) break;
            M = Mn;
        }
        skeep[g] = M;
        __syncwarp();
    }

    float* obds = out + (size_t)NB * NCLIP * 3;
    float* osc  = obds + 2 * NN;
    for (int g = 0; g < nG; g++) {
        int idx = 32 * g + lane;
        if (idx < cnt) {
            int gr = g_sgr[ob + idx];
            float f = ((skeep[g] >> lane) & 1u) ? 1.0f : 0.0f;
            obds[2 * gr]     = g_ss[ob + idx] * f;
            obds[2 * gr + 1] = g_se[ob + idx] * f;
            osc[gr]          = g_ssc[ob + idx] * f;
        }
    }
}

// ---------------------------------------------------------------------------
extern "C" void kernel_launch(void* const* d_in, const int* in_sizes, int n_in,
                              void* d_out, int out_size) {
    const float* gt    = (const float*)d_in[0];
    const float* pred  = (const float*)d_in[1];
    const float* score = (const float*)d_in[2];
    const int*   bidx  = (const int*)d_in[3];
    float* out = (float*)d_out;

    k1_kernel<<<NB + JCH * (NN / 256), 256>>>(gt, score, out);
    k2_kernel<<<NB, 256>>>(bidx, pred, score);
    k3_kernel<<<dim3(MAXG, NB), 256>>>();
    k4_kernel<<<NB, 32>>>(out);
}

// round 10
// speedup vs baseline: 1.7332x; 1.4354x over previous
#include <cuda_runtime.h>

#define NB    32
#define NN    8192
#define NCLIP 256
#define JCH   16          // j-chunks of 512 for partial rank
#define JSZ   512
#define CAPB  512         // per-batch capacity (mean 256, 16-sigma margin)
#define NWRD  (CAPB / 32) // 16 mask words per column
#define FULL  0xffffffffu

// Scratch (__device__ globals; allocation-free rule)
__device__ int g_part[JCH * NN];   // partial global ranks

// ---------------------------------------------------------------------------
// K1: blocks 0..31 gt_dist | blocks 32..543 partial rank (chunk-aligned diet)
// Chunk jc covers j in [512jc,512jc+512); i-block iblk covers [256iblk,+256).
// jc < iblk>>1  -> all j < i  -> ties count (>=)
// jc > iblk>>1  -> all j > i  -> strict (>)
// jc == iblk>>1 -> overlaps   -> exact tie-break expression
// ---------------------------------------------------------------------------
__global__ void k1_kernel(const float* __restrict__ gt,
                          const float* __restrict__ score,
                          float* __restrict__ out) {
    int blk = blockIdx.x;
    int tid = threadIdx.x;
    if (blk < NB) {
        int b = blk, c = tid;
        float s = gt[2 * b];
        float e = gt[2 * b + 1];
        float len  = 256.0f * (e - s);
        float cen0 = 256.0f * s;
        float cen1 = 256.0f * e;
        float cen2 = 128.0f * (s + e);
        float sgS  = 0.25f * len;
        float sgM  = 0.21f * len;
        float inv2sS = 1.0f / (2.0f * sgS * sgS);
        float inv2sM = 1.0f / (2.0f * sgM * sgM);
        float fc = (float)c;
        float d0 = fc - cen0, d1 = fc - cen1, d2 = fc - cen2;
        float* o = out + ((size_t)b * NCLIP + c) * 3;
        o[0] = expf(-d0 * d0 * inv2sS);
        o[1] = expf(-d1 * d1 * inv2sS);
        o[2] = expf(-d2 * d2 * inv2sM);
        return;
    }
    int q    = blk - NB;              // 0..511
    int jc   = q & (JCH - 1);         // 0..15
    int iblk = q >> 4;                // 0..31
    int i    = iblk * 256 + tid;
    int ibc  = iblk >> 1;             // chunk containing this i-block
    float si = score[i];
    const float4* s4 = (const float4*)score + jc * (JSZ / 4);
    int r = 0;
    if (jc < ibc) {                   // all j < i: ties count
#pragma unroll 8
        for (int t = 0; t < JSZ / 4; t++) {
            float4 v = s4[t];
            r += (v.x >= si) + (v.y >= si) + (v.z >= si) + (v.w >= si);
        }
    } else if (jc > ibc) {            // all j > i: strict
#pragma unroll 8
        for (int t = 0; t < JSZ / 4; t++) {
            float4 v = s4[t];
            r += (v.x > si) + (v.y > si) + (v.z > si) + (v.w > si);
        }
    } else {                          // overlapping chunk: exact tie-break
        int jbase = jc * JSZ;
#pragma unroll 8
        for (int t = 0; t < JSZ / 4; t++) {
            float4 v = s4[t];
            int j = jbase + 4 * t;
            r += (v.x > si) || (v.x == si && (j + 0) < i);
            r += (v.y > si) || (v.y == si && (j + 1) < i);
            r += (v.z > si) || (v.z == si && (j + 2) < i);
            r += (v.w > si) || (v.w == si && (j + 3) < i);
        }
    }
    g_part[jc * NN + i] = r;
}

// ---------------------------------------------------------------------------
// K2: one CTA (512 threads) per batch — offsets, stable sort, global rank,
// SMEM mask build, ballot-fixpoint greedy scan, writeback. All in SMEM.
// ---------------------------------------------------------------------------
__global__ void __launch_bounds__(512, 1)
k2_kernel(const int*   __restrict__ bidx,
          const float* __restrict__ pred,
          const float* __restrict__ score,
          float* __restrict__ out) {
    __shared__ float    rsc[CAPB];
    __shared__ float    ss[CAPB], se_[CAPB], sl[CAPB], ssc[CAPB];
    __shared__ int      sgr[CAPB];
    __shared__ unsigned sup[NWRD * CAPB];    // word-major masks, 32 KB
    __shared__ unsigned skeep[NWRD];
    __shared__ int      sob, soe;

    int b   = blockIdx.x;
    int tid = threadIdx.x;

    if (tid == 0) {
        int lo = 0, hi = NN;
        while (lo < hi) { int m = (lo + hi) >> 1; if (bidx[m] < b) lo = m + 1; else hi = m; }
        int ob = lo;
        hi = NN;
        while (lo < hi) { int m = (lo + hi) >> 1; if (bidx[m] < b + 1) lo = m + 1; else hi = m; }
        sob = ob; soe = lo;
    }
    __syncthreads();
    int ob  = sob;
    int cnt = soe - ob;
    if (cnt > CAPB) cnt = CAPB;
    if (cnt == 0) return;
    int nG = (cnt + 31) >> 5;

    if (tid < cnt) rsc[tid] = score[ob + tid];
    __syncthreads();

    // Phase 1: within-batch stable rank + global rank; scatter to sorted smem
    if (tid < cnt) {
        float si = rsc[tid];
        int wr = 0;
        for (int j = 0; j < cnt; j++) {
            float sj = rsc[j];
            wr += (sj > si) || (sj == si && j < tid);
        }
        int i = ob + tid;
        int r = 0;
#pragma unroll
        for (int jc = 0; jc < JCH; jc++) r += g_part[jc * NN + i];
        float2 p2 = ((const float2*)pred)[i];
        ss[wr]  = p2.x;
        se_[wr] = p2.y;
        sl[wr]  = p2.y - p2.x;
        ssc[wr] = si;
        sgr[wr] = r;
    }
    __syncthreads();

    // Phase 2: build lower-triangle suppression masks (word-major in smem)
    int Ttot = 16 * nG * (nG + 1);           // sum_g 32*(g+1)
    for (int p = tid; p < Ttot; p += 512) {
        int g = 0, base = 0;
        while (p >= base + 32 * (g + 1)) { base += 32 * (g + 1); g++; }
        int ofs = p - base;
        int w   = ofs >> 5;                  // 0..g
        int jl  = ofs & 31;
        int j   = 32 * g + jl;
        if (j >= cnt) continue;
        float sj = ss[j], ej = se_[j], lj = sl[j];
        unsigned word = 0;
        int rb = 32 * w;
#pragma unroll
        for (int k = 0; k < 32; k++) {
            float si_ = ss[rb + k], ei_ = se_[rb + k], li_ = sl[rb + k];
            float interc = fmaxf(fminf(ej, ei_) - fmaxf(sj, si_), 0.0f);
            float uni = lj + li_ - interc;
            float um  = fmaxf(uni, 1e-8f);
            float diff = interc - 0.5f * um;
            bool sp;
            if (fabsf(diff) <= 1e-6f * um) sp = (interc / um) > 0.5f;
            else                           sp = diff > 0.0f;
            if (sp) word |= 1u << k;
        }
        if (w == g) word &= (1u << jl) - 1u;     // only rows i < j
        sup[w * CAPB + j] = word;
    }
    __syncthreads();

    // Phase 3: ballot-fixpoint greedy scan (warp 0, masks in smem)
    if (tid < 32) {
        int lane = tid;
        for (int g = 0; g < nG; g++) {
            int j = 32 * g + lane;
            bool valid = j < cnt;
            unsigned dead = 0;
            for (int w = 0; w < g; w++)
                dead |= valid ? (sup[w * CAPB + j] & skeep[w]) : 0u;
            unsigned pend = valid ? sup[g * CAPB + j] : 0u;
            bool alive0 = valid && (dead == 0u);
            unsigned M = __ballot_sync(FULL, alive0);
            for (;;) {                           // unique fixpoint = greedy
                unsigned Mn = __ballot_sync(FULL, alive0 && ((pend & M) == 0u));
                if (Mn == M) break;
                M = Mn;
            }
            skeep[g] = M;
            __syncwarp();
        }
    }
    __syncthreads();

    // Phase 4: writeback at global sorted positions
    float* obds = out + (size_t)NB * NCLIP * 3;
    float* osc  = obds + 2 * NN;
    if (tid < cnt) {
        int gr = sgr[tid];
        float f = ((skeep[tid >> 5] >> (tid & 31)) & 1u) ? 1.0f : 0.0f;
        obds[2 * gr]     = ss[tid] * f;
        obds[2 * gr + 1] = se_[tid] * f;
        osc[gr]          = ssc[tid] * f;
    }
}

// ---------------------------------------------------------------------------
extern "C" void kernel_launch(void* const* d_in, const int* in_sizes, int n_in,
                              void* d_out, int out_size) {
    const float* gt    = (const float*)d_in[0];
    const float* pred  = (const float*)d_in[1];
    const float* score = (const float*)d_in[2];
    const int*   bidx  = (const int*)d_in[3];
    float* out = (float*)d_out;

    k1_kernel<<<NB + JCH * (NN / 256), 256>>>(gt, score, out);
    k2_kernel<<<NB, 512>>>(bidx, pred, score, out);
}

// round 11
// speedup vs baseline: 1.8429x; 1.0633x over previous
#include <cuda_runtime.h>

#define NB    32
#define NN    8192
#define NCLIP 256
#define JCH   16            // j-chunks of 512 for partial rank
#define JSZ   512
#define CAPB  512           // padded per-batch array stride
#define MAXG  12            // max 32-col groups (cnt <= 384, 8-sigma margin)
#define MAXC  (32 * MAXG)   // 384
#define FULL  0xffffffffu

// Scratch (__device__ globals; allocation-free rule)
__device__ int      g_off[NB + 1];
__device__ int      g_part[JCH * NN];          // partial global ranks
__device__ float    g_ss[NN + CAPB];           // per-batch sorted starts (+pad)
__device__ float    g_se[NN + CAPB];           // per-batch sorted ends   (+pad)
__device__ float    g_ssc[NN];                 // sorted scores
__device__ int      g_sidx[NN];                // sorted slot -> original index
__device__ unsigned g_sup[NB * MAXG * CAPB];   // masks, w-major

// ---------------------------------------------------------------------------
// K1: blocks 0..31 gt_dist | 32..63 per-batch sort | 64..575 rank partials
// ---------------------------------------------------------------------------
__global__ void k1_kernel(const float* __restrict__ gt,
                          const int*   __restrict__ bidx,
                          const float* __restrict__ pred,
                          const float* __restrict__ score,
                          float* __restrict__ out) {
    int blk = blockIdx.x;
    int tid = threadIdx.x;
    if (blk < NB) {                                    // ---- gt_dist ----
        int b = blk, c = tid;
        float s = gt[2 * b];
        float e = gt[2 * b + 1];
        float len  = 256.0f * (e - s);
        float cen0 = 256.0f * s;
        float cen1 = 256.0f * e;
        float cen2 = 128.0f * (s + e);
        float sgS  = 0.25f * len;
        float sgM  = 0.21f * len;
        float inv2sS = 1.0f / (2.0f * sgS * sgS);
        float inv2sM = 1.0f / (2.0f * sgM * sgM);
        float fc = (float)c;
        float d0 = fc - cen0, d1 = fc - cen1, d2 = fc - cen2;
        float* o = out + ((size_t)b * NCLIP + c) * 3;
        o[0] = expf(-d0 * d0 * inv2sS);
        o[1] = expf(-d1 * d1 * inv2sS);
        o[2] = expf(-d2 * d2 * inv2sM);
        return;
    }
    if (blk < 2 * NB) {                                // ---- per-batch sort ----
        int b = blk - NB;
        __shared__ int sob, soe;
        __shared__ float rsc[CAPB];
        if (tid == 0) {
            int lo = 0, hi = NN;
            while (lo < hi) { int m = (lo + hi) >> 1; if (bidx[m] < b) lo = m + 1; else hi = m; }
            int ob = lo;
            hi = NN;
            while (lo < hi) { int m = (lo + hi) >> 1; if (bidx[m] < b + 1) lo = m + 1; else hi = m; }
            sob = ob; soe = lo;
            g_off[b] = ob;
            if (b == NB - 1) g_off[NB] = NN;
        }
        __syncthreads();
        int ob  = sob;
        int cnt = soe - ob;
        if (cnt > MAXC) cnt = MAXC;
        for (int t = tid; t < cnt; t += 256) rsc[t] = score[ob + t];
        __syncthreads();
        for (int t = tid; t < cnt; t += 256) {
            float si = rsc[t];
            int wr = 0;
            for (int j = 0; j < cnt; j++) {
                float sj = rsc[j];
                wr += (sj > si) || (sj == si && j < t);
            }
            int i = ob + t;
            float2 p2 = ((const float2*)pred)[i];
            g_ss[ob + wr]   = p2.x;
            g_se[ob + wr]   = p2.y;
            g_ssc[ob + wr]  = si;
            g_sidx[ob + wr] = i;
        }
        return;
    }
    // ---- rank partials (chunk-aligned diet) ----
    int q    = blk - 2 * NB;          // 0..511
    int jc   = q & (JCH - 1);         // 0..15
    int iblk = q >> 4;                // 0..31
    int i    = iblk * 256 + tid;
    int ibc  = iblk >> 1;             // 512-chunk containing this i-block
    float si = score[i];
    const float4* s4 = (const float4*)score + jc * (JSZ / 4);
    int r = 0;
    if (jc < ibc) {                   // all j < i: ties count
#pragma unroll 8
        for (int t = 0; t < JSZ / 4; t++) {
            float4 v = s4[t];
            r += (v.x >= si) + (v.y >= si) + (v.z >= si) + (v.w >= si);
        }
    } else if (jc > ibc) {            // all j > i: strict
#pragma unroll 8
        for (int t = 0; t < JSZ / 4; t++) {
            float4 v = s4[t];
            r += (v.x > si) + (v.y > si) + (v.z > si) + (v.w > si);
        }
    } else {                          // overlapping chunk: exact tie-break
        int jbase = jc * JSZ;
#pragma unroll 8
        for (int t = 0; t < JSZ / 4; t++) {
            float4 v = s4[t];
            int j = jbase + 4 * t;
            r += (v.x > si) || (v.x == si && (j + 0) < i);
            r += (v.y > si) || (v.y == si && (j + 1) < i);
            r += (v.z > si) || (v.z == si && (j + 2) < i);
            r += (v.w > si) || (v.w == si && (j + 3) < i);
        }
    }
    g_part[jc * NN + i] = r;
}

// ---------------------------------------------------------------------------
// K2: mask build. CTA per (column-group g, batch b). Coalesced w-major writes.
// ---------------------------------------------------------------------------
__global__ void k2_kernel() {
    int g = blockIdx.x;               // 0..MAXG-1
    int b = blockIdx.y;
    int ob  = g_off[b];
    int cnt = g_off[b + 1] - ob;
    if (cnt > MAXC) cnt = MAXC;
    if (32 * g >= cnt) return;

    __shared__ float ss[MAXC], se_[MAXC], sl[MAXC];
    int tid  = threadIdx.x;
    int rows = 32 * (g + 1);
    for (int i = tid; i < rows; i += 256) {
        float s = g_ss[ob + i], e = g_se[ob + i];   // pad makes OOB-safe
        ss[i] = s; se_[i] = e; sl[i] = e - s;
    }
    __syncthreads();

    int jl = tid & 31;
    int wh = tid >> 5;
    int j  = 32 * g + jl;
    if (j >= cnt) return;
    float sj = ss[j], ej = se_[j], lj = sl[j];
    for (int w = wh; w <= g; w += 8) {
        unsigned word = 0;
        int rb = 32 * w;
#pragma unroll
        for (int k = 0; k < 32; k++) {
            float si_ = ss[rb + k], ei_ = se_[rb + k], li_ = sl[rb + k];
            float interc = fmaxf(fminf(ej, ei_) - fmaxf(sj, si_), 0.0f);
            float uni = lj + li_ - interc;
            float um  = fmaxf(uni, 1e-8f);
            float diff = interc - 0.5f * um;
            bool sp;
            if (fabsf(diff) <= 1e-6f * um) sp = (interc / um) > 0.5f;
            else                           sp = diff > 0.0f;
            if (sp) word |= 1u << k;
        }
        if (w == g) word &= (1u << jl) - 1u;         // only rows i < j
        g_sup[(b * MAXG + w) * CAPB + j] = word;     // coalesced across jl
    }
}

// ---------------------------------------------------------------------------
// K3: per-batch — SMEM-prefetched scan + rank finalize + writeback.
// ---------------------------------------------------------------------------
__global__ void k3_kernel(float* __restrict__ out) {
    __shared__ unsigned ssup[MAXG * MAXC];   // 18 KB
    __shared__ unsigned skeep[MAXG];
    int b   = blockIdx.x;
    int tid = threadIdx.x;
    int ob  = g_off[b];
    int cnt = g_off[b + 1] - ob;
    if (cnt > MAXC) cnt = MAXC;
    if (cnt == 0) return;
    int nG = (cnt + 31) >> 5;

    // Coalesced parallel prefetch of all mask words for this batch
    int jl32 = 32 * nG;
    for (int w = 0; w < nG; w++)
        for (int j = tid; j < jl32; j += 256)
            ssup[w * MAXC + j] = g_sup[(b * MAXG + w) * CAPB + j];
    __syncthreads();

    // Ballot-fixpoint greedy scan (warp 0, SMEM masks)
    if (tid < 32) {
        int lane = tid;
        for (int g = 0; g < nG; g++) {
            int j = 32 * g + lane;
            bool valid = j < cnt;
            unsigned dead = 0;
            for (int w = 0; w < g; w++)
                dead |= valid ? (ssup[w * MAXC + j] & skeep[w]) : 0u;
            unsigned pend = valid ? ssup[g * MAXC + j] : 0u;
            bool alive0 = valid && (dead == 0u);
            unsigned M = __ballot_sync(FULL, alive0);
            for (;;) {                           // unique fixpoint = greedy
                unsigned Mn = __ballot_sync(FULL, alive0 && ((pend & M) == 0u));
                if (Mn == M) break;
                M = Mn;
            }
            skeep[g] = M;
            __syncwarp();
        }
    }
    __syncthreads();

    // Rank finalize + writeback (all 256 threads)
    float* obds = out + (size_t)NB * NCLIP * 3;
    float* osc  = obds + 2 * NN;
    for (int t = tid; t < cnt; t += 256) {
        int i = g_sidx[ob + t];
        int r = 0;
#pragma unroll
        for (int jc = 0; jc < JCH; jc++) r += g_part[jc * NN + i];
        float f = ((skeep[t >> 5] >> (t & 31)) & 1u) ? 1.0f : 0.0f;
        obds[2 * r]     = g_ss[ob + t] * f;
        obds[2 * r + 1] = g_se[ob + t] * f;
        osc[r]          = g_ssc[ob + t] * f;
    }
}

// ---------------------------------------------------------------------------
extern "C" void kernel_launch(void* const* d_in, const int* in_sizes, int n_in,
                              void* d_out, int out_size) {
    const float* gt    = (const float*)d_in[0];
    const float* pred  = (const float*)d_in[1];
    const float* score = (const float*)d_in[2];
    const int*   bidx  = (const int*)d_in[3];
    float* out = (float*)d_out;

    k1_kernel<<<2 * NB + JCH * (NN / 256), 256>>>(gt, bidx, pred, score, out);
    k2_kernel<<<dim3(MAXG, NB), 256>>>();
    k3_kernel<<<NB, 256>>>(out);
}